// round 2
// baseline (speedup 1.0000x reference)
#include <cuda_runtime.h>

#define M_NODES 50000
#define K_NBR   32
#define DCH     256
// floor(32*0.45)=14 -> keep sorted ranks [14..17], mean of 4

__device__ float g_h[M_NODES * DCH];

// ---------------------------------------------------------------------------
// SGEMM: h[m][n] = sum_k x[m][k] * W[n][k]   (BM=BN=128, BK=16, 256 thr, 8x8)
// ---------------------------------------------------------------------------
__global__ void __launch_bounds__(256) sgemm_xWt(
    const float* __restrict__ A,   // x  [M, 256]
    const float* __restrict__ B)   // W  [256, 256]
{
    __shared__ float As[16][132];
    __shared__ float Bs[16][132];

    const int bm  = blockIdx.x * 128;
    const int bn  = blockIdx.y * 128;
    const int tid = threadIdx.x;
    const int tx  = tid & 15;
    const int ty  = tid >> 4;

    float acc[8][8];
#pragma unroll
    for (int i = 0; i < 8; i++)
#pragma unroll
        for (int j = 0; j < 8; j++) acc[i][j] = 0.0f;

#pragma unroll 1
    for (int kt = 0; kt < 256; kt += 16) {
#pragma unroll
        for (int l = 0; l < 2; l++) {
            int t   = tid + l * 256;
            int row = t >> 2;
            int k4  = (t & 3) * 4;

            float4 av = make_float4(0.f, 0.f, 0.f, 0.f);
            if (bm + row < M_NODES)
                av = *reinterpret_cast<const float4*>(&A[(size_t)(bm + row) * 256 + kt + k4]);
            As[k4 + 0][row] = av.x;
            As[k4 + 1][row] = av.y;
            As[k4 + 2][row] = av.z;
            As[k4 + 3][row] = av.w;

            float4 bv = *reinterpret_cast<const float4*>(&B[(size_t)(bn + row) * 256 + kt + k4]);
            Bs[k4 + 0][row] = bv.x;
            Bs[k4 + 1][row] = bv.y;
            Bs[k4 + 2][row] = bv.z;
            Bs[k4 + 3][row] = bv.w;
        }
        __syncthreads();

#pragma unroll
        for (int kk = 0; kk < 16; kk++) {
            float a[8], b[8];
            *reinterpret_cast<float4*>(&a[0]) = *reinterpret_cast<const float4*>(&As[kk][ty * 8 + 0]);
            *reinterpret_cast<float4*>(&a[4]) = *reinterpret_cast<const float4*>(&As[kk][ty * 8 + 4]);
            *reinterpret_cast<float4*>(&b[0]) = *reinterpret_cast<const float4*>(&Bs[kk][tx * 8 + 0]);
            *reinterpret_cast<float4*>(&b[4]) = *reinterpret_cast<const float4*>(&Bs[kk][tx * 8 + 4]);
#pragma unroll
            for (int i = 0; i < 8; i++)
#pragma unroll
                for (int j = 0; j < 8; j++)
                    acc[i][j] = fmaf(a[i], b[j], acc[i][j]);
        }
        __syncthreads();
    }

#pragma unroll
    for (int i = 0; i < 8; i++) {
        int m = bm + ty * 8 + i;
        if (m < M_NODES) {
            float* dst = &g_h[(size_t)m * 256 + bn + tx * 8];
            *reinterpret_cast<float4*>(dst + 0) = make_float4(acc[i][0], acc[i][1], acc[i][2], acc[i][3]);
            *reinterpret_cast<float4*>(dst + 4) = make_float4(acc[i][4], acc[i][5], acc[i][6], acc[i][7]);
        }
    }
}

// ---------------------------------------------------------------------------
// Gather + partial selection network + trimmed mean.
//   1. Batcher odd-even mergesort (63 CE) on each half of 16  -> two ascending
//   2. half-cleaner min/max(v[i], v[31-i])                     -> 16 smallest
//      (bitonic) in v[0..15], 16 largest (bitonic) in v[16..31]
//   3. top-2 of bitonic lower via 3 max-reductions (8+4+2 ops) = ranks 14,15
//      bottom-2 of bitonic upper via 3 min-reductions          = ranks 16,17
// ~316 lane-ops vs 480 for the full bitonic sort.
// ---------------------------------------------------------------------------
__global__ void __launch_bounds__(256) gather_trim(
    const void* __restrict__ nbrs_raw,
    float* __restrict__ out)
{
    __shared__ int sn[K_NBR];

    const int node = blockIdx.x;
    const int tid  = threadIdx.x;

    if (tid < K_NBR) {
        // dtype sniff: if int64, ALL hi 32-bit words of elems 0..31 are zero
        // (indices < 50000). Identical data in every block -> identical result.
        const int* w = reinterpret_cast<const int*>(nbrs_raw);
        unsigned m = __ballot_sync(0xffffffffu, w[2 * tid + 1] == 0);
        bool is64 = (m == 0xffffffffu);

        long long idx = is64
            ? reinterpret_cast<const long long*>(nbrs_raw)[(size_t)node * K_NBR + tid]
            : (long long)reinterpret_cast<const int*>(nbrs_raw)[(size_t)node * K_NBR + tid];
        sn[tid] = (int)idx * DCH;
    }
    __syncthreads();

    float v[K_NBR];
#pragma unroll
    for (int k = 0; k < K_NBR; k++)
        v[k] = __ldg(&g_h[sn[k] + tid]);

    // --- Batcher odd-even mergesort, each 16-half ascending (63 CE each) ---
#pragma unroll
    for (int half = 0; half < 2; half++) {
        const int base = half * 16;
#pragma unroll
        for (int p = 1; p < 16; p <<= 1) {
#pragma unroll
            for (int k = p; k >= 1; k >>= 1) {
#pragma unroll
                for (int j = k & (p - 1); j + k < 16; j += 2 * k) {
#pragma unroll
                    for (int i = 0; i < k; i++) {
                        if (i + j + k < 16 &&
                            (i + j) / (2 * p) == (i + j + k) / (2 * p)) {
                            int a = base + i + j, b = base + i + j + k;
                            float mn = fminf(v[a], v[b]);
                            float mx = fmaxf(v[a], v[b]);
                            v[a] = mn;
                            v[b] = mx;
                        }
                    }
                }
            }
        }
    }

    // --- half-cleaner: v[0..15] = 16 smallest (bitonic), v[16..31] = 16 largest ---
#pragma unroll
    for (int i = 0; i < 16; i++) {
        float a = v[i], b = v[31 - i];
        v[i]      = fminf(a, b);
        v[31 - i] = fmaxf(a, b);
    }

    // --- top-2 of bitonic v[0..15] (ranks 14,15) ---
#pragma unroll
    for (int j = 8; j >= 2; j >>= 1)
#pragma unroll
        for (int i = 0; i < j; i++)
            v[i] = fmaxf(v[i], v[i + j]);

    // --- bottom-2 of bitonic v[16..31] (ranks 16,17) ---
#pragma unroll
    for (int j = 8; j >= 2; j >>= 1)
#pragma unroll
        for (int i = 0; i < j; i++)
            v[16 + i] = fminf(v[16 + i], v[16 + i + j]);

    out[(size_t)node * DCH + tid] = (v[0] + v[1] + v[16] + v[17]) * 0.25f;
}

// ---------------------------------------------------------------------------
extern "C" void kernel_launch(void* const* d_in, const int* in_sizes, int n_in,
                              void* d_out, int out_size)
{
    const float* x    = nullptr;
    const void*  nbrs = nullptr;
    const float* W    = nullptr;

    for (int i = 0; i < n_in; i++) {
        if      (in_sizes[i] == M_NODES * DCH)   x    = (const float*)d_in[i];
        else if (in_sizes[i] == M_NODES * K_NBR) nbrs = d_in[i];
        else if (in_sizes[i] == DCH * DCH)       W    = (const float*)d_in[i];
    }
    if (!x)    x    = (const float*)d_in[0];
    if (!nbrs) nbrs = d_in[1];
    if (!W)    W    = (const float*)d_in[2];

    dim3 ggrid((M_NODES + 127) / 128, 2);
    sgemm_xWt<<<ggrid, 256>>>(x, W);

    gather_trim<<<M_NODES, 256>>>(nbrs, (float*)d_out);
}

// round 3
// speedup vs baseline: 2.4326x; 2.4326x over previous
#include <cuda_runtime.h>

#define M_NODES 50000
#define K_NBR   32
#define DCH     256
// floor(32*0.45)=14 -> keep sorted ranks [14..17], mean of 4

__device__ float g_h[M_NODES * DCH];

// ---------------------------------------------------------------------------
// SGEMM: h[m][n] = sum_k x[m][k] * W[n][k]   (BM=BN=128, BK=16, 256 thr, 8x8)
// ---------------------------------------------------------------------------
__global__ void __launch_bounds__(256) sgemm_xWt(
    const float* __restrict__ A,   // x  [M, 256]
    const float* __restrict__ B)   // W  [256, 256]
{
    __shared__ float As[16][132];
    __shared__ float Bs[16][132];

    const int bm  = blockIdx.x * 128;
    const int bn  = blockIdx.y * 128;
    const int tid = threadIdx.x;
    const int tx  = tid & 15;
    const int ty  = tid >> 4;

    float acc[8][8];
#pragma unroll
    for (int i = 0; i < 8; i++)
#pragma unroll
        for (int j = 0; j < 8; j++) acc[i][j] = 0.0f;

#pragma unroll 1
    for (int kt = 0; kt < 256; kt += 16) {
#pragma unroll
        for (int l = 0; l < 2; l++) {
            int t   = tid + l * 256;
            int row = t >> 2;
            int k4  = (t & 3) * 4;

            float4 av = make_float4(0.f, 0.f, 0.f, 0.f);
            if (bm + row < M_NODES)
                av = *reinterpret_cast<const float4*>(&A[(size_t)(bm + row) * 256 + kt + k4]);
            As[k4 + 0][row] = av.x;
            As[k4 + 1][row] = av.y;
            As[k4 + 2][row] = av.z;
            As[k4 + 3][row] = av.w;

            float4 bv = *reinterpret_cast<const float4*>(&B[(size_t)(bn + row) * 256 + kt + k4]);
            Bs[k4 + 0][row] = bv.x;
            Bs[k4 + 1][row] = bv.y;
            Bs[k4 + 2][row] = bv.z;
            Bs[k4 + 3][row] = bv.w;
        }
        __syncthreads();

#pragma unroll
        for (int kk = 0; kk < 16; kk++) {
            float a[8], b[8];
            *reinterpret_cast<float4*>(&a[0]) = *reinterpret_cast<const float4*>(&As[kk][ty * 8 + 0]);
            *reinterpret_cast<float4*>(&a[4]) = *reinterpret_cast<const float4*>(&As[kk][ty * 8 + 4]);
            *reinterpret_cast<float4*>(&b[0]) = *reinterpret_cast<const float4*>(&Bs[kk][tx * 8 + 0]);
            *reinterpret_cast<float4*>(&b[4]) = *reinterpret_cast<const float4*>(&Bs[kk][tx * 8 + 4]);
#pragma unroll
            for (int i = 0; i < 8; i++)
#pragma unroll
                for (int j = 0; j < 8; j++)
                    acc[i][j] = fmaf(a[i], b[j], acc[i][j]);
        }
        __syncthreads();
    }

#pragma unroll
    for (int i = 0; i < 8; i++) {
        int m = bm + ty * 8 + i;
        if (m < M_NODES) {
            float* dst = &g_h[(size_t)m * 256 + bn + tx * 8];
            *reinterpret_cast<float4*>(dst + 0) = make_float4(acc[i][0], acc[i][1], acc[i][2], acc[i][3]);
            *reinterpret_cast<float4*>(dst + 4) = make_float4(acc[i][4], acc[i][5], acc[i][6], acc[i][7]);
        }
    }
}

// compare-exchange with LITERAL indices only -> guaranteed register residency
#define CE(a, b) { float _mn = fminf(v[a], v[b]); \
                   float _mx = fmaxf(v[a], v[b]); \
                   v[a] = _mn; v[b] = _mx; }

// Batcher odd-even mergesort of v[o+0..o+15], ascending (63 comparators),
// fully explicit (pairs generated from the iterative Batcher algorithm).
#define OEMS16(o) \
    /* p=1,k=1 */ \
    CE(o+0,o+1)  CE(o+2,o+3)   CE(o+4,o+5)   CE(o+6,o+7) \
    CE(o+8,o+9)  CE(o+10,o+11) CE(o+12,o+13) CE(o+14,o+15) \
    /* p=2,k=2 */ \
    CE(o+0,o+2)  CE(o+1,o+3)   CE(o+4,o+6)   CE(o+5,o+7) \
    CE(o+8,o+10) CE(o+9,o+11)  CE(o+12,o+14) CE(o+13,o+15) \
    /* p=2,k=1 */ \
    CE(o+1,o+2)  CE(o+5,o+6)   CE(o+9,o+10)  CE(o+13,o+14) \
    /* p=4,k=4 */ \
    CE(o+0,o+4)  CE(o+1,o+5)   CE(o+2,o+6)   CE(o+3,o+7) \
    CE(o+8,o+12) CE(o+9,o+13)  CE(o+10,o+14) CE(o+11,o+15) \
    /* p=4,k=2 */ \
    CE(o+2,o+4)  CE(o+3,o+5)   CE(o+10,o+12) CE(o+11,o+13) \
    /* p=4,k=1 */ \
    CE(o+1,o+2)  CE(o+3,o+4)   CE(o+5,o+6) \
    CE(o+9,o+10) CE(o+11,o+12) CE(o+13,o+14) \
    /* p=8,k=8 */ \
    CE(o+0,o+8)  CE(o+1,o+9)   CE(o+2,o+10)  CE(o+3,o+11) \
    CE(o+4,o+12) CE(o+5,o+13)  CE(o+6,o+14)  CE(o+7,o+15) \
    /* p=8,k=4 */ \
    CE(o+4,o+8)  CE(o+5,o+9)   CE(o+6,o+10)  CE(o+7,o+11) \
    /* p=8,k=2 */ \
    CE(o+2,o+4)  CE(o+3,o+5)   CE(o+6,o+8) \
    CE(o+7,o+9)  CE(o+10,o+12) CE(o+11,o+13) \
    /* p=8,k=1 */ \
    CE(o+1,o+2)  CE(o+3,o+4)   CE(o+5,o+6)   CE(o+7,o+8) \
    CE(o+9,o+10) CE(o+11,o+12) CE(o+13,o+14)

// ---------------------------------------------------------------------------
// Gather + partial selection + trimmed mean. One block per node, thread = chan.
//   1. OEMS16 on each half                      (2 x 63 CE)
//   2. half-cleaner v[i] <-> v[31-i]            (16 CE)
//      -> v[0..15]=16 smallest (bitonic), v[16..31]=16 largest (bitonic)
//   3. ranks 14,15 = top-2 of bitonic lower  (max-reductions 8+4+2)
//      ranks 16,17 = bot-2 of bitonic upper  (min-reductions 8+4+2)
// ---------------------------------------------------------------------------
__global__ void __launch_bounds__(256) gather_trim(
    const void* __restrict__ nbrs_raw,
    float* __restrict__ out)
{
    __shared__ int sn[K_NBR];

    const int node = blockIdx.x;
    const int tid  = threadIdx.x;

    if (tid < K_NBR) {
        // dtype sniff: if int64, all hi words of elems 0..31 are zero
        const int* w = reinterpret_cast<const int*>(nbrs_raw);
        unsigned m = __ballot_sync(0xffffffffu, w[2 * tid + 1] == 0);
        bool is64 = (m == 0xffffffffu);

        long long idx = is64
            ? reinterpret_cast<const long long*>(nbrs_raw)[(size_t)node * K_NBR + tid]
            : (long long)reinterpret_cast<const int*>(nbrs_raw)[(size_t)node * K_NBR + tid];
        sn[tid] = (int)idx * DCH;
    }
    __syncthreads();

    float v[K_NBR];
#pragma unroll
    for (int k = 0; k < K_NBR; k++)
        v[k] = __ldg(&g_h[sn[k] + tid]);

    OEMS16(0)
    OEMS16(16)

    // half-cleaner
#pragma unroll
    for (int i = 0; i < 16; i++) {
        float a = v[i], b = v[31 - i];
        v[i]      = fminf(a, b);
        v[31 - i] = fmaxf(a, b);
    }

    // top-2 of bitonic v[0..15]
#pragma unroll
    for (int j = 8; j >= 2; j >>= 1)
#pragma unroll
        for (int i = 0; i < j; i++)
            v[i] = fmaxf(v[i], v[i + j]);

    // bottom-2 of bitonic v[16..31]
#pragma unroll
    for (int j = 8; j >= 2; j >>= 1)
#pragma unroll
        for (int i = 0; i < j; i++)
            v[16 + i] = fminf(v[16 + i], v[16 + i + j]);

    out[(size_t)node * DCH + tid] = (v[0] + v[1] + v[16] + v[17]) * 0.25f;
}

// ---------------------------------------------------------------------------
extern "C" void kernel_launch(void* const* d_in, const int* in_sizes, int n_in,
                              void* d_out, int out_size)
{
    const float* x    = nullptr;
    const void*  nbrs = nullptr;
    const float* W    = nullptr;

    for (int i = 0; i < n_in; i++) {
        if      (in_sizes[i] == M_NODES * DCH)   x    = (const float*)d_in[i];
        else if (in_sizes[i] == M_NODES * K_NBR) nbrs = d_in[i];
        else if (in_sizes[i] == DCH * DCH)       W    = (const float*)d_in[i];
    }
    if (!x)    x    = (const float*)d_in[0];
    if (!nbrs) nbrs = d_in[1];
    if (!W)    W    = (const float*)d_in[2];

    dim3 ggrid((M_NODES + 127) / 128, 2);
    sgemm_xWt<<<ggrid, 256>>>(x, W);

    gather_trim<<<M_NODES, 256>>>(nbrs, (float*)d_out);
}

// round 5
// speedup vs baseline: 2.9345x; 1.2063x over previous
#include <cuda_runtime.h>
#include <cuda_bf16.h>
#include <cstdint>

#define M_NODES 50000
#define K_NBR   32
#define DCH     256

__device__ float         g_h[M_NODES * DCH];
__device__ __nv_bfloat16 g_whi[DCH * DCH];
__device__ __nv_bfloat16 g_wlo[DCH * DCH];

// ===================== W split (tiny: 256KB traffic) ========================
__global__ void __launch_bounds__(256) convert_w(const float* __restrict__ w) {
    size_t i4 = (size_t)blockIdx.x * 256 + threadIdx.x;
    if (i4 * 4 >= (size_t)DCH * DCH) return;
    float4 f = *reinterpret_cast<const float4*>(w + i4 * 4);
    __nv_bfloat162 h01 = __floats2bfloat162_rn(f.x, f.y);
    __nv_bfloat162 h23 = __floats2bfloat162_rn(f.z, f.w);
    __nv_bfloat162 l01 = __floats2bfloat162_rn(f.x - __bfloat162float(h01.x),
                                               f.y - __bfloat162float(h01.y));
    __nv_bfloat162 l23 = __floats2bfloat162_rn(f.z - __bfloat162float(h23.x),
                                               f.w - __bfloat162float(h23.y));
    reinterpret_cast<uint2*>(g_whi)[i4] =
        make_uint2(*reinterpret_cast<uint32_t*>(&h01), *reinterpret_cast<uint32_t*>(&h23));
    reinterpret_cast<uint2*>(g_wlo)[i4] =
        make_uint2(*reinterpret_cast<uint32_t*>(&l01), *reinterpret_cast<uint32_t*>(&l23));
}

// ===================== mma.sync bf16 split GEMM =============================
// h[m][n] = x_hi*W_hi + x_hi*W_lo + x_lo*W_hi   (virtual K = 3*256 = 768)
// Block: 128x128, 8 warps (4m x 2n), warp tile 32x64, BK=32, double-buffered.
#define AS_LD 40   // halves per smem row (32 data + 8 pad) -> 80B stride

__device__ __forceinline__ uint32_t smem_u32(const void* p) {
    uint32_t a;
    asm("{ .reg .u64 t; cvta.to.shared.u64 t, %1; cvt.u32.u64 %0, t; }" : "=r"(a) : "l"(p));
    return a;
}
__device__ __forceinline__ void ldsm_x4(uint32_t* r, uint32_t addr) {
    asm volatile("ldmatrix.sync.aligned.m8n8.x4.shared.b16 {%0,%1,%2,%3}, [%4];"
                 : "=r"(r[0]), "=r"(r[1]), "=r"(r[2]), "=r"(r[3]) : "r"(addr));
}
__device__ __forceinline__ void ldsm_x2(uint32_t* r, uint32_t addr) {
    asm volatile("ldmatrix.sync.aligned.m8n8.x2.shared.b16 {%0,%1}, [%2];"
                 : "=r"(r[0]), "=r"(r[1]) : "r"(addr));
}
__device__ __forceinline__ void mma_bf16(float* d, const uint32_t* a, const uint32_t* b) {
    asm volatile(
        "mma.sync.aligned.m16n8k16.row.col.f32.bf16.bf16.f32 "
        "{%0,%1,%2,%3}, {%4,%5,%6,%7}, {%8,%9}, {%0,%1,%2,%3};"
        : "+f"(d[0]), "+f"(d[1]), "+f"(d[2]), "+f"(d[3])
        : "r"(a[0]), "r"(a[1]), "r"(a[2]), "r"(a[3]), "r"(b[0]), "r"(b[1]));
}

__global__ void __launch_bounds__(256) gemm_mma(const float* __restrict__ x) {
    __shared__ __align__(16) __nv_bfloat16 As[2][128 * AS_LD];
    __shared__ __align__(16) __nv_bfloat16 Bs[2][128 * AS_LD];

    const int tid  = threadIdx.x;
    const int bm   = blockIdx.x * 128;
    const int bn   = blockIdx.y * 128;
    const int warp = tid >> 5, lane = tid & 31;
    const int mw   = warp >> 1, nw = warp & 1;

    float acc[2][8][4];
#pragma unroll
    for (int mt = 0; mt < 2; mt++)
#pragma unroll
        for (int nt = 0; nt < 8; nt++)
#pragma unroll
            for (int q = 0; q < 4; q++) acc[mt][nt][q] = 0.0f;

    float4 ar[4];
    uint2  br[4];

    auto load_g = [&](int kt) {
        const int seg = kt >> 3;                 // 0: hi*Whi  1: hi*Wlo  2: lo*Whi
        const int kk  = (kt & 7) * 32;
        const __nv_bfloat16* wsrc = (seg == 1) ? g_wlo : g_whi;
#pragma unroll
        for (int l = 0; l < 4; l++) {
            int t = tid + l * 256, r = t >> 3, j = t & 7;
            int row = bm + r;
            float4 v = make_float4(0.f, 0.f, 0.f, 0.f);
            if (row < M_NODES)
                v = *reinterpret_cast<const float4*>(x + (size_t)row * DCH + kk + j * 4);
            ar[l] = v;
            br[l] = *reinterpret_cast<const uint2*>(wsrc + (size_t)(bn + r) * DCH + kk + j * 4);
        }
    };

    auto sts = [&](int kt, int buf) {
        const bool hi = ((kt >> 3) < 2);
#pragma unroll
        for (int l = 0; l < 4; l++) {
            int t = tid + l * 256, r = t >> 3, j = t & 7;
            float4 v = ar[l];
            __nv_bfloat162 h01 = __floats2bfloat162_rn(v.x, v.y);
            __nv_bfloat162 h23 = __floats2bfloat162_rn(v.z, v.w);
            __nv_bfloat162 p0, p1;
            if (hi) { p0 = h01; p1 = h23; }
            else {
                p0 = __floats2bfloat162_rn(v.x - __bfloat162float(h01.x),
                                           v.y - __bfloat162float(h01.y));
                p1 = __floats2bfloat162_rn(v.z - __bfloat162float(h23.x),
                                           v.w - __bfloat162float(h23.y));
            }
            *reinterpret_cast<uint2*>(&As[buf][r * AS_LD + j * 4]) =
                make_uint2(*reinterpret_cast<uint32_t*>(&p0), *reinterpret_cast<uint32_t*>(&p1));
            *reinterpret_cast<uint2*>(&Bs[buf][r * AS_LD + j * 4]) = br[l];
        }
    };

    auto compute = [&](int buf) {
        const uint32_t as_b = smem_u32(&As[buf][0]);
        const uint32_t bs_b = smem_u32(&Bs[buf][0]);
#pragma unroll
        for (int ks = 0; ks < 2; ks++) {
            const int k0 = ks * 16;
            uint32_t afrag[2][4];
#pragma unroll
            for (int mt = 0; mt < 2; mt++) {
                uint32_t addr = as_b + 2u * ((mw * 32 + mt * 16 + (lane & 15)) * AS_LD +
                                             (lane >> 4) * 8 + k0);
                ldsm_x4(afrag[mt], addr);
            }
            uint32_t bfrag[8][2];
#pragma unroll
            for (int nt = 0; nt < 8; nt++) {
                uint32_t addr = bs_b + 2u * ((nw * 64 + nt * 8 + (lane & 7)) * AS_LD +
                                             ((lane >> 3) & 1) * 8 + k0);
                ldsm_x2(bfrag[nt], addr);
            }
#pragma unroll
            for (int mt = 0; mt < 2; mt++)
#pragma unroll
                for (int nt = 0; nt < 8; nt++)
                    mma_bf16(acc[mt][nt], afrag[mt], bfrag[nt]);
        }
    };

    load_g(0);
    sts(0, 0);
    __syncthreads();

#pragma unroll 1
    for (int kt = 0; kt < 24; kt++) {
        const int buf = kt & 1;
        if (kt < 23) load_g(kt + 1);
        compute(buf);
        if (kt < 23) sts(kt + 1, buf ^ 1);
        __syncthreads();
    }

    // epilogue: acc -> g_h (fp32)
#pragma unroll
    for (int mt = 0; mt < 2; mt++) {
        const int m0 = bm + mw * 32 + mt * 16 + (lane >> 2);
#pragma unroll
        for (int nt = 0; nt < 8; nt++) {
            const int n = bn + nw * 64 + nt * 8 + (lane & 3) * 2;
            if (m0 < M_NODES)
                *reinterpret_cast<float2*>(&g_h[(size_t)m0 * DCH + n]) =
                    make_float2(acc[mt][nt][0], acc[mt][nt][1]);
            if (m0 + 8 < M_NODES)
                *reinterpret_cast<float2*>(&g_h[(size_t)(m0 + 8) * DCH + n]) =
                    make_float2(acc[mt][nt][2], acc[mt][nt][3]);
        }
    }
}

// ===================== gather + selection network (round-3, proven) =========
#define CE(a, b) { float _mn = fminf(v[a], v[b]); \
                   float _mx = fmaxf(v[a], v[b]); \
                   v[a] = _mn; v[b] = _mx; }

#define OEMS16(o) \
    CE(o+0,o+1)  CE(o+2,o+3)   CE(o+4,o+5)   CE(o+6,o+7) \
    CE(o+8,o+9)  CE(o+10,o+11) CE(o+12,o+13) CE(o+14,o+15) \
    CE(o+0,o+2)  CE(o+1,o+3)   CE(o+4,o+6)   CE(o+5,o+7) \
    CE(o+8,o+10) CE(o+9,o+11)  CE(o+12,o+14) CE(o+13,o+15) \
    CE(o+1,o+2)  CE(o+5,o+6)   CE(o+9,o+10)  CE(o+13,o+14) \
    CE(o+0,o+4)  CE(o+1,o+5)   CE(o+2,o+6)   CE(o+3,o+7) \
    CE(o+8,o+12) CE(o+9,o+13)  CE(o+10,o+14) CE(o+11,o+15) \
    CE(o+2,o+4)  CE(o+3,o+5)   CE(o+10,o+12) CE(o+11,o+13) \
    CE(o+1,o+2)  CE(o+3,o+4)   CE(o+5,o+6) \
    CE(o+9,o+10) CE(o+11,o+12) CE(o+13,o+14) \
    CE(o+0,o+8)  CE(o+1,o+9)   CE(o+2,o+10)  CE(o+3,o+11) \
    CE(o+4,o+12) CE(o+5,o+13)  CE(o+6,o+14)  CE(o+7,o+15) \
    CE(o+4,o+8)  CE(o+5,o+9)   CE(o+6,o+10)  CE(o+7,o+11) \
    CE(o+2,o+4)  CE(o+3,o+5)   CE(o+6,o+8) \
    CE(o+7,o+9)  CE(o+10,o+12) CE(o+11,o+13) \
    CE(o+1,o+2)  CE(o+3,o+4)   CE(o+5,o+6)   CE(o+7,o+8) \
    CE(o+9,o+10) CE(o+11,o+12) CE(o+13,o+14)

__global__ void __launch_bounds__(256) gather_trim(
    const void* __restrict__ nbrs_raw,
    float* __restrict__ out)
{
    __shared__ int sn[K_NBR];

    const int node = blockIdx.x;
    const int tid  = threadIdx.x;

    if (tid < K_NBR) {
        const int* w = reinterpret_cast<const int*>(nbrs_raw);
        unsigned m = __ballot_sync(0xffffffffu, w[2 * tid + 1] == 0);
        bool is64 = (m == 0xffffffffu);
        long long idx = is64
            ? reinterpret_cast<const long long*>(nbrs_raw)[(size_t)node * K_NBR + tid]
            : (long long)reinterpret_cast<const int*>(nbrs_raw)[(size_t)node * K_NBR + tid];
        sn[tid] = (int)idx * DCH;
    }
    __syncthreads();

    float v[K_NBR];
#pragma unroll
    for (int k = 0; k < K_NBR; k++)
        v[k] = __ldg(&g_h[sn[k] + tid]);

    OEMS16(0)
    OEMS16(16)

#pragma unroll
    for (int i = 0; i < 16; i++) {
        float a = v[i], b = v[31 - i];
        v[i]      = fminf(a, b);
        v[31 - i] = fmaxf(a, b);
    }
#pragma unroll
    for (int j = 8; j >= 2; j >>= 1)
#pragma unroll
        for (int i = 0; i < j; i++)
            v[i] = fmaxf(v[i], v[i + j]);
#pragma unroll
    for (int j = 8; j >= 2; j >>= 1)
#pragma unroll
        for (int i = 0; i < j; i++)
            v[16 + i] = fminf(v[16 + i], v[16 + i + j]);

    out[(size_t)node * DCH + tid] = (v[0] + v[1] + v[16] + v[17]) * 0.25f;
}

// ===================== launch ===============================================
extern "C" void kernel_launch(void* const* d_in, const int* in_sizes, int n_in,
                              void* d_out, int out_size)
{
    const float* x    = nullptr;
    const void*  nbrs = nullptr;
    const float* W    = nullptr;

    for (int i = 0; i < n_in; i++) {
        if      (in_sizes[i] == M_NODES * DCH)   x    = (const float*)d_in[i];
        else if (in_sizes[i] == M_NODES * K_NBR) nbrs = d_in[i];
        else if (in_sizes[i] == DCH * DCH)       W    = (const float*)d_in[i];
    }
    if (!x)    x    = (const float*)d_in[0];
    if (!nbrs) nbrs = d_in[1];
    if (!W)    W    = (const float*)d_in[2];

    convert_w<<<(DCH * DCH / 4 + 255) / 256, 256>>>(W);

    dim3 ggrid((M_NODES + 127) / 128, 2);
    gemm_mma<<<ggrid, 256>>>(x);

    gather_trim<<<M_NODES, 256>>>(nbrs, (float*)d_out);
}